// round 2
// baseline (speedup 1.0000x reference)
#include <cuda_runtime.h>
#include <cuda_bf16.h>

// FinDiffNonUniform: yd[i,b] = sum_s w[i,s] * y[i + off[i,s], b]
// N=8192 rows, B=4096 cols, S=7 stencil, fp32.
//
// R2: kernel is LTS(L2-path)-throughput bound, not DRAM bound. Reduce
// L2->SM read amplification from 1.75x (TR=8, full window) to 1.19x
// (TR=32, ROLLING 9-row register window: 7-row stencil + 2 prefetch).
// All window indices are compile-time (full unroll) -> register renaming,
// no local spills, no dynamic indexing.

#define S_W 7
#define TR 32
#define TPB 256
#define VEC 4
#define PF 2
#define BUF (S_W + PF)            // 9 live rows
#define COLS_PER_BLOCK (TPB * VEC)

__global__ __launch_bounds__(TPB, 4)
void findiff_roll_kernel(const float* __restrict__ y,
                         const float* __restrict__ coef,
                         const int* __restrict__ offs,
                         float* __restrict__ out,
                         int N, int B)
{
    __shared__ float s_w[TR * S_W];
    __shared__ int   s_o[TR * S_W];
    __shared__ int   s_centered;

    const int t  = threadIdx.x;
    const int i0 = blockIdx.y * TR;

    if (t == 0) s_centered = 1;
    __syncthreads();

    // cooperative load of this tile's 32x7 coefficient / offset slab
    for (int k = t; k < TR * S_W; k += TPB) {
        int gidx = i0 * S_W + k;
        if (gidx < N * S_W) {
            s_w[k] = coef[gidx];
            int o  = offs[gidx];
            s_o[k] = o;
            if (o != (k % S_W) - 3) s_centered = 0;
        } else {
            s_w[k] = 0.0f;
            s_o[k] = 0;
        }
    }
    __syncthreads();

    const int col = blockIdx.x * COLS_PER_BLOCK + t * VEC;
    if (col >= B) return;

    const bool interior = (i0 >= 3) && (i0 + TR + 2 <= N - 1) && s_centered;

    if (interior) {
        // ---- fast path: rolling register window, static offsets s-3 ----
        const float* base = y   + (size_t)(i0 - 3) * (size_t)B + col;
        float*       obase = out + (size_t)i0       * (size_t)B + col;

        float4 buf[BUF];
        #pragma unroll
        for (int k = 0; k < BUF; ++k)
            buf[k] = *reinterpret_cast<const float4*>(base + (size_t)k * (size_t)B);

        #pragma unroll
        for (int r = 0; r < TR; ++r) {
            // prefetch row index (BUF + r) of the TR+6-row span, if needed
            float4 nxt = make_float4(0.f, 0.f, 0.f, 0.f);
            if (BUF + r <= TR + 5)
                nxt = *reinterpret_cast<const float4*>(
                          base + (size_t)(BUF + r) * (size_t)B);

            float4 acc = make_float4(0.f, 0.f, 0.f, 0.f);
            #pragma unroll
            for (int s = 0; s < S_W; ++s) {
                const float  w = s_w[r * S_W + s];
                const float4 v = buf[s];
                acc.x = fmaf(w, v.x, acc.x);
                acc.y = fmaf(w, v.y, acc.y);
                acc.z = fmaf(w, v.z, acc.z);
                acc.w = fmaf(w, v.w, acc.w);
            }
            *reinterpret_cast<float4*>(obase + (size_t)r * (size_t)B) = acc;

            // shift window (pure register renaming under full unroll)
            #pragma unroll
            for (int k = 0; k < BUF - 1; ++k) buf[k] = buf[k + 1];
            buf[BUF - 1] = nxt;
        }
    } else {
        // ---- generic path: per-row gather (boundary tiles only) ----
        #pragma unroll 4
        for (int r = 0; r < TR; ++r) {
            const int i = i0 + r;
            if (i >= N) break;
            float4 acc = make_float4(0.f, 0.f, 0.f, 0.f);
            #pragma unroll
            for (int s = 0; s < S_W; ++s) {
                const float w = s_w[r * S_W + s];
                const int   j = i + s_o[r * S_W + s];
                const float4 v = *reinterpret_cast<const float4*>(
                    y + (size_t)j * (size_t)B + col);
                acc.x = fmaf(w, v.x, acc.x);
                acc.y = fmaf(w, v.y, acc.y);
                acc.z = fmaf(w, v.z, acc.z);
                acc.w = fmaf(w, v.w, acc.w);
            }
            *reinterpret_cast<float4*>(out + (size_t)i * (size_t)B + col) = acc;
        }
    }
}

// Fully generic scalar fallback (any N, B).
__global__ void findiff_scalar_kernel(const float* __restrict__ y,
                                      const float* __restrict__ coef,
                                      const int* __restrict__ offs,
                                      float* __restrict__ out,
                                      int N, int B)
{
    const long long total = (long long)N * B;
    for (long long idx = (long long)blockIdx.x * blockDim.x + threadIdx.x;
         idx < total;
         idx += (long long)gridDim.x * blockDim.x) {
        const int i = (int)(idx / B);
        const int b = (int)(idx % B);
        float acc = 0.f;
        #pragma unroll
        for (int s = 0; s < S_W; ++s) {
            const float w = coef[i * S_W + s];
            const int   j = i + offs[i * S_W + s];
            acc = fmaf(w, y[(size_t)j * (size_t)B + b], acc);
        }
        out[idx] = acc;
    }
}

extern "C" void kernel_launch(void* const* d_in, const int* in_sizes, int n_in,
                              void* d_out, int out_size)
{
    const float* y    = (const float*)d_in[0];
    const float* coef = (const float*)d_in[1];
    const int*   offs = (const int*)d_in[2];
    float* out = (float*)d_out;

    const int N = in_sizes[1] / S_W;       // all_coefficients is [N, 7]
    const int B = in_sizes[0] / N;         // y is [N, B]

    if ((B % COLS_PER_BLOCK) == 0) {
        dim3 grid(B / COLS_PER_BLOCK, (N + TR - 1) / TR);
        findiff_roll_kernel<<<grid, TPB>>>(y, coef, offs, out, N, B);
    } else {
        const long long total = (long long)N * B;
        int blocks = (int)((total + 255) / 256);
        if (blocks > 65535 * 32) blocks = 65535 * 32;
        findiff_scalar_kernel<<<blocks, 256>>>(y, coef, offs, out, N, B);
    }
}

// round 3
// speedup vs baseline: 1.2399x; 1.2399x over previous
#include <cuda_runtime.h>
#include <cuda_bf16.h>

// FinDiffNonUniform: yd[i,b] = sum_s w[i,s] * y[i + off[i,s], b]
// N=8192 rows, B=4096 cols, S=7 stencil, fp32.
//
// R3: kernel is latency/concurrency bound (DRAM stuck at ~59% with occ
// ~42-45% in R1/R2). Keep the front-batched 14-row window (MLP=14, static
// indices) but halve per-thread register footprint with VEC=2 (float2)
// so occupancy rises to ~75% (6 CTAs/SM @ <=42 regs). L2 read
// amplification stays 1.75x (not binding).

#define S_W 7
#define TR 8
#define TPB 256
#define VEC 2
#define WIN (TR + 6)              // 14-row window
#define COLS_PER_BLOCK (TPB * VEC)

__global__ __launch_bounds__(TPB, 6)
void findiff_v2_kernel(const float* __restrict__ y,
                       const float* __restrict__ coef,
                       const int* __restrict__ offs,
                       float* __restrict__ out,
                       int N, int B)
{
    __shared__ float s_w[TR * S_W];
    __shared__ int   s_o[TR * S_W];
    __shared__ int   s_centered;

    const int t  = threadIdx.x;
    const int i0 = blockIdx.y * TR;

    if (t == 0) s_centered = 1;
    __syncthreads();

    if (t < TR * S_W) {
        int gidx = i0 * S_W + t;
        if (gidx < N * S_W) {
            s_w[t] = coef[gidx];
            int o  = offs[gidx];
            s_o[t] = o;
            if (o != (t % S_W) - 3) s_centered = 0;
        } else {
            s_w[t] = 0.0f;
            s_o[t] = 0;
        }
    }
    __syncthreads();

    const int col = blockIdx.x * COLS_PER_BLOCK + t * VEC;
    if (col >= B) return;

    const bool interior = (i0 >= 3) && (i0 + TR + 2 <= N - 1) && s_centered;

    if (interior) {
        // ---- fast path: front-batched register window, offsets = s-3 ----
        float2 win[WIN];
        const float* base = y + (size_t)(i0 - 3) * (size_t)B + col;
        #pragma unroll
        for (int k = 0; k < WIN; ++k)
            win[k] = *reinterpret_cast<const float2*>(base + (size_t)k * (size_t)B);

        float* obase = out + (size_t)i0 * (size_t)B + col;
        #pragma unroll
        for (int r = 0; r < TR; ++r) {
            float2 acc = make_float2(0.f, 0.f);
            #pragma unroll
            for (int s = 0; s < S_W; ++s) {
                const float  w = s_w[r * S_W + s];
                const float2 v = win[r + s];
                acc.x = fmaf(w, v.x, acc.x);
                acc.y = fmaf(w, v.y, acc.y);
            }
            *reinterpret_cast<float2*>(obase + (size_t)r * (size_t)B) = acc;
        }
    } else {
        // ---- generic path: per-row gather (boundary tiles only) ----
        #pragma unroll
        for (int r = 0; r < TR; ++r) {
            const int i = i0 + r;
            if (i >= N) break;
            float2 acc = make_float2(0.f, 0.f);
            #pragma unroll
            for (int s = 0; s < S_W; ++s) {
                const float w = s_w[r * S_W + s];
                const int   j = i + s_o[r * S_W + s];
                const float2 v = *reinterpret_cast<const float2*>(
                    y + (size_t)j * (size_t)B + col);
                acc.x = fmaf(w, v.x, acc.x);
                acc.y = fmaf(w, v.y, acc.y);
            }
            *reinterpret_cast<float2*>(out + (size_t)i * (size_t)B + col) = acc;
        }
    }
}

// Fully generic scalar fallback (any N, B).
__global__ void findiff_scalar_kernel(const float* __restrict__ y,
                                      const float* __restrict__ coef,
                                      const int* __restrict__ offs,
                                      float* __restrict__ out,
                                      int N, int B)
{
    const long long total = (long long)N * B;
    for (long long idx = (long long)blockIdx.x * blockDim.x + threadIdx.x;
         idx < total;
         idx += (long long)gridDim.x * blockDim.x) {
        const int i = (int)(idx / B);
        const int b = (int)(idx % B);
        float acc = 0.f;
        #pragma unroll
        for (int s = 0; s < S_W; ++s) {
            const float w = coef[i * S_W + s];
            const int   j = i + offs[i * S_W + s];
            acc = fmaf(w, y[(size_t)j * (size_t)B + b], acc);
        }
        out[idx] = acc;
    }
}

extern "C" void kernel_launch(void* const* d_in, const int* in_sizes, int n_in,
                              void* d_out, int out_size)
{
    const float* y    = (const float*)d_in[0];
    const float* coef = (const float*)d_in[1];
    const int*   offs = (const int*)d_in[2];
    float* out = (float*)d_out;

    const int N = in_sizes[1] / S_W;       // all_coefficients is [N, 7]
    const int B = in_sizes[0] / N;         // y is [N, B]

    if ((B % COLS_PER_BLOCK) == 0) {
        dim3 grid(B / COLS_PER_BLOCK, (N + TR - 1) / TR);
        findiff_v2_kernel<<<grid, TPB>>>(y, coef, offs, out, N, B);
    } else {
        const long long total = (long long)N * B;
        int blocks = (int)((total + 255) / 256);
        if (blocks > 65535 * 32) blocks = 65535 * 32;
        findiff_scalar_kernel<<<blocks, 256>>>(y, coef, offs, out, N, B);
    }
}